// round 8
// baseline (speedup 1.0000x reference)
#include <cuda_runtime.h>
#include <cstdint>

// ItemEncoder R8: R4 (TMA-bulk ring, 8 consumer warps, W in registers)
//                 + intra-warp software pipelining of the epilogue.
//   out[t,:] = M[ids[t],:] @ W^T + b ; 12800 tokens, D=2000, O=8.
//
//  - 1 CTA / SM, 288 threads: warps 0-7 consumers, warp 8 producer (lane 0).
//  - 6-slot x 32000 B smem ring, cp.async.bulk rows (8000 B contiguous).
//  - Consumer per stage k:
//      collapse acc(k) -> cur (acc regs freed)
//      wait full(k+1); compute acc(k+1); arrive empty(k+1)   <- early release
//      butterfly(cur); red[k&1]; ONE bar; warp0 stores k
//    So epilogue(k) overlaps DRAM fetch + compute of k+1; per-stage cost
//    ~max(compute, epilogue) instead of the R4 sum.

static constexpr int NTOK  = 12800;
static constexpr int D     = 2000;
static constexpr int ROWB  = D * 4;          // 8000 B
static constexpr int QPR   = D / 4;          // 500
static constexpr int STOK  = 4;
static constexpr int NSTG  = NTOK / STOK;    // 3200
static constexpr int NTHR  = 288;
static constexpr int NCONS = 256;
static constexpr int NBUF  = 6;
static constexpr int STAGEB  = STOK * ROWB;  // 32000
static constexpr int BSTRIDE = 32256;        // +256 B zeroed pad (quads 500..511)
static constexpr int SM_RED  = NBUF * BSTRIDE;       // 193536; red = 2 x 1024 B
static constexpr int SM_MBAR = SM_RED + 2048;
static constexpr int SM_TOT  = SM_MBAR + NBUF * 16;

__device__ __forceinline__ void ffma2(unsigned long long &acc,
                                      unsigned long long a,
                                      unsigned long long b) {
    asm("fma.rn.f32x2 %0, %1, %2, %0;" : "+l"(acc) : "l"(a), "l"(b));
}
__device__ __forceinline__ void mbar_init(uint32_t a, uint32_t cnt) {
    asm volatile("mbarrier.init.shared.b64 [%0], %1;" :: "r"(a), "r"(cnt) : "memory");
}
__device__ __forceinline__ void mbar_expect_tx(uint32_t a, uint32_t bytes) {
    asm volatile("mbarrier.arrive.expect_tx.shared.b64 _, [%0], %1;"
                 :: "r"(a), "r"(bytes) : "memory");
}
__device__ __forceinline__ void mbar_arrive(uint32_t a) {
    asm volatile("mbarrier.arrive.shared.b64 _, [%0];" :: "r"(a) : "memory");
}
__device__ __forceinline__ void mbar_wait(uint32_t a, uint32_t parity) {
    asm volatile(
        "{\n\t.reg .pred P;\n\t"
        "WL_%=:\n\t"
        "mbarrier.try_wait.parity.acquire.cta.shared::cta.b64 P, [%0], %1, 0x989680;\n\t"
        "@P bra WD_%=;\n\t"
        "bra WL_%=;\n\t"
        "WD_%=:\n\t}"
        :: "r"(a), "r"(parity) : "memory");
}
__device__ __forceinline__ void bulk_cp(uint32_t smem_dst, const void* gmem_src,
                                        uint32_t bytes, uint32_t mbar) {
    asm volatile(
        "cp.async.bulk.shared::cta.global.mbarrier::complete_tx::bytes "
        "[%0], [%1], %2, [%3];"
        :: "r"(smem_dst), "l"(gmem_src), "r"(bytes), "r"(mbar) : "memory");
}
__device__ __forceinline__ void bar_cons() {     // consumers only (256 threads)
    asm volatile("bar.sync 1, %0;" :: "n"(NCONS) : "memory");
}

__global__ void __launch_bounds__(NTHR, 1)
gather_proj_r8(const int*   __restrict__ ids,
               const float* __restrict__ M,
               const float* __restrict__ W,
               const float* __restrict__ bias,
               float*       __restrict__ out)
{
    extern __shared__ char smem[];
    const uint32_t smem_u32 = (uint32_t)__cvta_generic_to_shared(smem);
    const int tid  = threadIdx.x;
    const int lane = tid & 31;
    const int wid  = tid >> 5;

    const int gridn  = gridDim.x;
    const int s0     = blockIdx.x;
    const int nLocal = (NSTG - s0 + gridn - 1) / gridn;

    auto fullb  = [&](int s) -> uint32_t { return smem_u32 + SM_MBAR + s * 16; };
    auto emptyb = [&](int s) -> uint32_t { return smem_u32 + SM_MBAR + s * 16 + 8; };

    // ---- init ----
    if (tid == 0) {
#pragma unroll
        for (int s = 0; s < NBUF; ++s) {
            mbar_init(fullb(s), 1);        // armed by producer expect_tx
            mbar_init(emptyb(s), NCONS);   // all consumer threads arrive
        }
    }
    if (tid < NBUF * 16) {                 // zero 6 x 256 B pads
        int b = tid >> 4, q = tid & 15;
        *(float4*)(smem + b * BSTRIDE + STAGEB + q * 16) =
            make_float4(0.f, 0.f, 0.f, 0.f);
    }
    __syncthreads();

    if (wid == 8) {
        // ================= producer =================
        if (lane == 0) {
            const char* Mb = (const char*)M;
            int phase = 1;                 // fresh barriers: first waits pass
            for (int k = 0; k < nLocal; ++k) {
                const int slot = k % NBUF;
                mbar_wait(emptyb(slot), phase);
                const int4 ii = __ldg((const int4*)ids + (s0 + k * gridn));
                const uint32_t dst = smem_u32 + slot * BSTRIDE;
                mbar_expect_tx(fullb(slot), STAGEB);
                bulk_cp(dst,            Mb + (size_t)ii.x * ROWB, ROWB, fullb(slot));
                bulk_cp(dst + ROWB,     Mb + (size_t)ii.y * ROWB, ROWB, fullb(slot));
                bulk_cp(dst + 2 * ROWB, Mb + (size_t)ii.z * ROWB, ROWB, fullb(slot));
                bulk_cp(dst + 3 * ROWB, Mb + (size_t)ii.w * ROWB, ROWB, fullb(slot));
                if (slot == NBUF - 1) phase ^= 1;
            }
        }
        return;
    }

    // ================= consumers (warps 0-7) =================
    const float bval = __ldg(bias + (lane & 7));

    // W into registers: this warp's quads q = wid*64 + it*32 + lane (zeroed OOB)
    ulonglong2 w[2][8];
#pragma unroll
    for (int it = 0; it < 2; ++it) {
        const int q = wid * 64 + it * 32 + lane;
#pragma unroll
        for (int o = 0; o < 8; ++o) {
            if (q < QPR) w[it][o] = __ldg((const ulonglong2*)W + o * QPR + q);
            else         w[it][o] = make_ulonglong2(0ull, 0ull);
        }
    }

    float* red = (float*)(smem + SM_RED);
    unsigned long long acc[4][8];

    // compute stage residing in ring slot `slot` into acc, then free the slot
    auto compute = [&](int slot) {
        const char* buf = smem + slot * BSTRIDE;
#pragma unroll
        for (int t = 0; t < 4; ++t)
#pragma unroll
            for (int o = 0; o < 8; ++o) acc[t][o] = 0ull;
#pragma unroll
        for (int it = 0; it < 2; ++it) {
            const int q = wid * 64 + it * 32 + lane;   // 500..511 hit pad, w=0
            ulonglong2 v[4];
#pragma unroll
            for (int t = 0; t < 4; ++t)
                v[t] = *(const ulonglong2*)(buf + t * ROWB + q * 16);
#pragma unroll
            for (int t = 0; t < 4; ++t)
#pragma unroll
                for (int o = 0; o < 8; ++o) {
                    ffma2(acc[t][o], v[t].x, w[it][o].x);
                    ffma2(acc[t][o], v[t].y, w[it][o].y);
                }
        }
        mbar_arrive(emptyb(slot));   // release: prior smem reads ordered
    };

    int wslot = 0, wphase = 0;       // cursor for the wait/compute stream
    auto adv = [&]() { if (++wslot == NBUF) { wslot = 0; wphase ^= 1; } };

    // prime: stage 0
    mbar_wait(fullb(wslot), wphase);
    compute(wslot);
    adv();

    for (int k = 0; k < nLocal; ++k) {
        // ---- collapse acc(k) -> cur; acc registers become free ----
        float cur[32];
#pragma unroll
        for (int t = 0; t < 4; ++t)
#pragma unroll
            for (int o = 0; o < 8; ++o) {
                const unsigned long long a = acc[t][o];
                cur[t * 8 + o] = __uint_as_float((unsigned)a) +
                                 __uint_as_float((unsigned)(a >> 32));
            }

        // ---- fetch+compute stage k+1 (overlaps epilogue below) ----
        if (k + 1 < nLocal) {
            mbar_wait(fullb(wslot), wphase);
            compute(wslot);
            adv();
        }

        // ---- epilogue for stage k: butterfly transpose-reduce ----
#pragma unroll
        for (int off = 16; off >= 1; off >>= 1) {
            const bool up = (lane & off) != 0;
#pragma unroll
            for (int j = 0; j < off; ++j) {
                float keep = up ? cur[j + off] : cur[j];
                float give = up ? cur[j] : cur[j + off];
                keep += __shfl_xor_sync(0xffffffffu, give, off);
                cur[j] = keep;
            }
        }
        // lane holds partial of output value `lane` (token lane>>3, out lane&7)
        float* redk = red + (k & 1) * 256;   // double buffer -> single bar
        redk[wid * 32 + lane] = cur[0];
        bar_cons();
        if (wid == 0) {
            float s = bval;
#pragma unroll
            for (int w8 = 0; w8 < 8; ++w8) s += redk[w8 * 32 + lane];
            out[(size_t)(s0 + k * gridn) * 32 + lane] = s;
        }
    }
}

extern "C" void kernel_launch(void* const* d_in, const int* in_sizes, int n_in,
                              void* d_out, int out_size) {
    const int*   ids  = (const int*)  d_in[0];
    const float* M    = (const float*)d_in[1];
    const float* W    = (const float*)d_in[2];
    const float* bias = (const float*)d_in[3];
    float*       out  = (float*)d_out;

    cudaFuncSetAttribute(gather_proj_r8,
                         cudaFuncAttributeMaxDynamicSharedMemorySize, SM_TOT);

    int nsm = 148;
    cudaDeviceGetAttribute(&nsm, cudaDevAttrMultiProcessorCount, 0);

    gather_proj_r8<<<nsm, NTHR, SM_TOT>>>(ids, M, W, bias, out);
}

// round 10
// speedup vs baseline: 1.8776x; 1.8776x over previous
#include <cuda_runtime.h>
#include <cstdint>

// ItemEncoder R10: R9 (TMA-bulk ring + 16 thin consumer warps, inline
// producer) with the smem layout bug fixed: red needs 4096 B (16 warps x
// 2 buffers), R9 reserved 2048 and odd stages clobbered the mbarriers.
//   out[t,:] = M[ids[t],:] @ W^T + b ; 12800 tokens, D=2000, O=8.

static constexpr int NTOK  = 12800;
static constexpr int D     = 2000;
static constexpr int ROWB  = D * 4;          // 8000 B
static constexpr int QPR   = D / 4;          // 500
static constexpr int STOK  = 4;
static constexpr int NSTG  = NTOK / STOK;    // 3200
static constexpr int NTHR  = 512;
static constexpr int NBUF  = 6;
static constexpr int LOOKAHEAD = NBUF - 1;   // 5 stages in flight
static constexpr int STAGEB  = STOK * ROWB;  // 32000
static constexpr int BSTRIDE = 32256;        // +256 B zeroed pad (quads 500..511)
static constexpr int SM_RED  = NBUF * BSTRIDE;       // 193536
static constexpr int SM_MBAR = SM_RED + 4096;        // red: 2 x 512 floats = 4096 B
static constexpr int SM_TOT  = SM_MBAR + NBUF * 8;   // 6 full-mbarriers

__device__ __forceinline__ void ffma2(unsigned long long &acc,
                                      unsigned long long a,
                                      unsigned long long b) {
    asm("fma.rn.f32x2 %0, %1, %2, %0;" : "+l"(acc) : "l"(a), "l"(b));
}
__device__ __forceinline__ void mbar_init(uint32_t a, uint32_t cnt) {
    asm volatile("mbarrier.init.shared.b64 [%0], %1;" :: "r"(a), "r"(cnt) : "memory");
}
__device__ __forceinline__ void mbar_expect_tx(uint32_t a, uint32_t bytes) {
    asm volatile("mbarrier.arrive.expect_tx.shared.b64 _, [%0], %1;"
                 :: "r"(a), "r"(bytes) : "memory");
}
__device__ __forceinline__ void mbar_wait(uint32_t a, uint32_t parity) {
    asm volatile(
        "{\n\t.reg .pred P;\n\t"
        "WL_%=:\n\t"
        "mbarrier.try_wait.parity.acquire.cta.shared::cta.b64 P, [%0], %1, 0x989680;\n\t"
        "@P bra WD_%=;\n\t"
        "bra WL_%=;\n\t"
        "WD_%=:\n\t}"
        :: "r"(a), "r"(parity) : "memory");
}
__device__ __forceinline__ void bulk_cp(uint32_t smem_dst, const void* gmem_src,
                                        uint32_t bytes, uint32_t mbar) {
    asm volatile(
        "cp.async.bulk.shared::cta.global.mbarrier::complete_tx::bytes "
        "[%0], [%1], %2, [%3];"
        :: "r"(smem_dst), "l"(gmem_src), "r"(bytes), "r"(mbar) : "memory");
}

__global__ void __launch_bounds__(NTHR, 1)
gather_proj_r10(const int*   __restrict__ ids,
                const float* __restrict__ M,
                const float* __restrict__ W,
                const float* __restrict__ bias,
                float*       __restrict__ out)
{
    extern __shared__ char smem[];
    const uint32_t smem_u32 = (uint32_t)__cvta_generic_to_shared(smem);
    const int tid  = threadIdx.x;
    const int lane = tid & 31;
    const int wid  = tid >> 5;

    const int gridn  = gridDim.x;
    const int s0     = blockIdx.x;
    const int nLocal = (NSTG - s0 + gridn - 1) / gridn;

    auto fullb = [&](int s) -> uint32_t { return smem_u32 + SM_MBAR + s * 8; };

    // ---- init: full mbarriers + zero ring pads ----
    if (tid == 0) {
#pragma unroll
        for (int s = 0; s < NBUF; ++s) mbar_init(fullb(s), 1);
    }
    if (tid < NBUF * 16) {                 // zero 6 x 256 B pads
        int b = tid >> 4, qq = tid & 15;
        *(float4*)(smem + b * BSTRIDE + STAGEB + qq * 16) =
            make_float4(0.f, 0.f, 0.f, 0.f);
    }

    // ---- W into registers: warp w owns quads q = 32w + lane (zeroed OOB) ----
    const int q = wid * 32 + lane;         // 0..511 (500..511 masked by W=0)
    ulonglong2 w[8];
#pragma unroll
    for (int o = 0; o < 8; ++o) {
        if (q < QPR) w[o] = __ldg((const ulonglong2*)W + o * QPR + q);
        else         w[o] = make_ulonglong2(0ull, 0ull);
    }
    const float bval = __ldg(bias + (lane & 7));
    const char* Mb = (const char*)M;

    __syncthreads();                       // mbarriers + pads visible

    // ---- producer state (warp 15 lane 0 only) ----
    const bool isProd = (wid == 15) && (lane == 0);
    int4 nid;                              // ids for the NEXT stage to issue
    if (isProd) {
        nid = __ldg((const int4*)ids + s0);
        // prologue: issue stages 0..LOOKAHEAD-1
#pragma unroll
        for (int j = 0; j < LOOKAHEAD; ++j) {
            if (j < nLocal) {
                const uint32_t dst = smem_u32 + (j % NBUF) * BSTRIDE;
                mbar_expect_tx(fullb(j % NBUF), STAGEB);
                bulk_cp(dst,            Mb + (size_t)nid.x * ROWB, ROWB, fullb(j % NBUF));
                bulk_cp(dst + ROWB,     Mb + (size_t)nid.y * ROWB, ROWB, fullb(j % NBUF));
                bulk_cp(dst + 2 * ROWB, Mb + (size_t)nid.z * ROWB, ROWB, fullb(j % NBUF));
                bulk_cp(dst + 3 * ROWB, Mb + (size_t)nid.w * ROWB, ROWB, fullb(j % NBUF));
                if (j + 1 < nLocal)
                    nid = __ldg((const int4*)ids + (s0 + (j + 1) * gridn));
            }
        }
    }

    float* red = (float*)(smem + SM_RED);
    int slot = 0, phase = 0;

    for (int k = 0; k < nLocal; ++k) {
        // ---- inline producer: issue stage k+5 into slot (k+5)%NBUF ----
        // Safe: __syncthreads at end of stage k-1 proved that slot was
        // fully consumed (it last held stage k-1); issued after the bar
        // in program order.
        if (isProd) {
            const int j = k + LOOKAHEAD;
            if (j < nLocal) {
                const int js = j % NBUF;
                const uint32_t dst = smem_u32 + js * BSTRIDE;
                mbar_expect_tx(fullb(js), STAGEB);
                bulk_cp(dst,            Mb + (size_t)nid.x * ROWB, ROWB, fullb(js));
                bulk_cp(dst + ROWB,     Mb + (size_t)nid.y * ROWB, ROWB, fullb(js));
                bulk_cp(dst + 2 * ROWB, Mb + (size_t)nid.z * ROWB, ROWB, fullb(js));
                bulk_cp(dst + 3 * ROWB, Mb + (size_t)nid.w * ROWB, ROWB, fullb(js));
                if (j + 1 < nLocal)     // LDG pipelined one stage ahead
                    nid = __ldg((const int4*)ids + (s0 + (j + 1) * gridn));
            }
        }

        // ---- wait for stage k, compute ----
        mbar_wait(fullb(slot), phase);
        const char* buf = smem + slot * BSTRIDE;

        unsigned long long acc[4][8];
#pragma unroll
        for (int t = 0; t < 4; ++t)
#pragma unroll
            for (int o = 0; o < 8; ++o) acc[t][o] = 0ull;

        {
            ulonglong2 v[4];
#pragma unroll
            for (int t = 0; t < 4; ++t)   // q in 500..511 hits zeroed pad (t=3)
                v[t] = *(const ulonglong2*)(buf + t * ROWB + q * 16);
#pragma unroll
            for (int t = 0; t < 4; ++t)
#pragma unroll
                for (int o = 0; o < 8; ++o) {
                    ffma2(acc[t][o], v[t].x, w[o].x);
                    ffma2(acc[t][o], v[t].y, w[o].y);
                }
        }

        // ---- collapse f32x2 -> 32 scalars, butterfly transpose-reduce ----
        float cur[32];
#pragma unroll
        for (int t = 0; t < 4; ++t)
#pragma unroll
            for (int o = 0; o < 8; ++o) {
                const unsigned long long a = acc[t][o];
                cur[t * 8 + o] = __uint_as_float((unsigned)a) +
                                 __uint_as_float((unsigned)(a >> 32));
            }
#pragma unroll
        for (int off = 16; off >= 1; off >>= 1) {
            const bool up = (lane & off) != 0;
#pragma unroll
            for (int j = 0; j < off; ++j) {
                float keep = up ? cur[j + off] : cur[j];
                float give = up ? cur[j] : cur[j + off];
                keep += __shfl_xor_sync(0xffffffffu, give, off);
                cur[j] = keep;
            }
        }

        // lane holds partial of output value `lane` (token lane>>3, out lane&7)
        float* redk = red + (k & 1) * 512;
        redk[wid * 32 + lane] = cur[0];
        __syncthreads();                   // red visible; slot k fully read

        if (wid == 0) {
            float s = bval;
#pragma unroll
            for (int w16 = 0; w16 < 16; ++w16) s += redk[w16 * 32 + lane];
            out[(size_t)(s0 + k * gridn) * 32 + lane] = s;
        }

        if (++slot == NBUF) { slot = 0; phase ^= 1; }
    }
}

extern "C" void kernel_launch(void* const* d_in, const int* in_sizes, int n_in,
                              void* d_out, int out_size) {
    const int*   ids  = (const int*)  d_in[0];
    const float* M    = (const float*)d_in[1];
    const float* W    = (const float*)d_in[2];
    const float* bias = (const float*)d_in[3];
    float*       out  = (float*)d_out;

    cudaFuncSetAttribute(gather_proj_r10,
                         cudaFuncAttributeMaxDynamicSharedMemorySize, SM_TOT);

    int nsm = 148;
    cudaDeviceGetAttribute(&nsm, cudaDevAttrMultiProcessorCount, 0);

    gather_proj_r10<<<nsm, NTHR, SM_TOT>>>(ids, M, W, bias, out);
}